// round 10
// baseline (speedup 1.0000x reference)
#include <cuda_runtime.h>
#include <cuda_bf16.h>
#include <cuda_fp8.h>
#include <float.h>

#define B_IMG 8
#define C_IN 64
#define H_IMG 288
#define W_IMG 512
#define NPIX (H_IMG * W_IMG)
#define NUM_FRAMES 9
#define K_ROIS 2
#define NCAND 32

// ---------------- scratch (device globals; no allocation allowed) ----------------
__device__ __align__(16) unsigned char g_h1[(size_t)B_IMG * 64 * H_IMG * W_IMG]; // e4m3, 75 MB
__device__ __align__(16) float g_heat[(size_t)B_IMG * NPIX];
__device__ int   g_cand[B_IMG * NCAND];
__device__ float g_rlogit[B_IMG * NCAND];

// ---------------- mma.sync fp8 m16n8k32, row.col, fp32 accum ----------------
__device__ __forceinline__ void mma16832(float* d,
    unsigned a0, unsigned a1, unsigned a2, unsigned a3, unsigned b0, unsigned b1) {
  asm volatile(
    "mma.sync.aligned.m16n8k32.row.col.f32.e4m3.e4m3.f32 "
    "{%0,%1,%2,%3}, {%4,%5,%6,%7}, {%8,%9}, {%0,%1,%2,%3};\n"
    : "+f"(d[0]), "+f"(d[1]), "+f"(d[2]), "+f"(d[3])
    : "r"(a0), "r"(a1), "r"(a2), "r"(a3), "r"(b0), "r"(b1));
}

__device__ __forceinline__ void ldsm_x4(unsigned& r0, unsigned& r1, unsigned& r2, unsigned& r3,
                                        unsigned addr) {
  asm volatile("ldmatrix.sync.aligned.m8n8.x4.shared.b16 {%0,%1,%2,%3}, [%4];\n"
    : "=r"(r0), "=r"(r1), "=r"(r2), "=r"(r3) : "r"(addr));
}

__device__ __forceinline__ unsigned char f2e4m3(float v) {
  return (unsigned char)__nv_cvt_float_to_fp8(v, __NV_SATFINITE, __NV_E4M3);
}

// smem geometry (e4m3 bytes), 16B-aligned strides for ldmatrix:
// xs pixel stride 80 B (80%128=80 -> rows hit distinct 16B bank-groups)
// ws row stride 592 B (592%128=80 -> same conflict-free pattern)
#define XPITCH 80
#define WPITCH 592
#define XS_BYTES (10 * 66 * XPITCH)     // 52800
#define WS1_BYTES (64 * WPITCH)         // 37888
#define SMEM1 (XS_BYTES + WS1_BYTES)    // 90688
#define WS2_BYTES (32 * WPITCH)         // 18944
#define SMEM2 (XS_BYTES + WS2_BYTES)    // 71744

// refine smem layout (floats)
#define ROFF_WS1 0                       // 64*577
#define ROFF_XP  (64 * 577)              // 64*28
#define ROFF_H1  (ROFF_XP + 64 * 28)     // 9*65
#define ROFF_PART (ROFF_H1 + 9 * 65)     // 32*9
#define ROFF_S2  (ROFF_PART + 32 * 9)    // 32
#define RSMEM_FLOATS (ROFF_S2 + 32)
#define RSMEM_BYTES (RSMEM_FLOATS * 4)   // ~158.5 KB

// ================= conv1: 64->64 3x3 SAME + ReLU, e4m3 out =================
// tile: 64 px wide x 8 rows, all 64 out ch. 512 threads / 16 warps.
__global__ __launch_bounds__(512) void conv1_kernel(
    const float* __restrict__ x, const float* __restrict__ w1, const float* __restrict__ b1) {
  extern __shared__ char smem[];
  unsigned char* xs = (unsigned char*)smem;
  unsigned char* ws = (unsigned char*)(smem + XS_BYTES);
  const int tid = threadIdx.x;
  const int n  = blockIdx.z;
  const int h0 = blockIdx.y * 8;
  const int w0 = blockIdx.x * 64;

  // ws[m][tap*64 + c] = e4m3(w1[m,c,tap])
  for (int i = tid; i < 64 * 576; i += 512) {
    int m = i / 576, rem = i - m * 576;
    int c = rem / 9, tap = rem - c * 9;
    ws[m * WPITCH + tap * 64 + c] = f2e4m3(w1[i]);
  }
  // xs[(r*66+col)*80 + c]
  for (int i = tid; i < 10 * 64 * 66; i += 512) {
    int col = i % 66;
    int t = i / 66;
    int c = t & 63, r = t >> 6;
    int h = h0 - 1 + r, w = w0 - 1 + col;
    float v = 0.f;
    if ((unsigned)h < (unsigned)H_IMG && (unsigned)w < (unsigned)W_IMG)
      v = x[((n * C_IN + c) * H_IMG + h) * W_IMG + w];
    xs[(r * 66 + col) * XPITCH + c] = f2e4m3(v);
  }
  __syncthreads();

  const int lane = tid & 31, wid = tid >> 5;
  const int g = lane >> 2, tg = lane & 3;
  const int wn = wid & 7;       // output row 0..7
  const int wh = wid >> 3;      // channel half
  const int m0 = wh * 32;

  const unsigned ws_sh = (unsigned)__cvta_generic_to_shared(ws);
  const unsigned xs_sh = (unsigned)__cvta_generic_to_shared(xs);
  const unsigned aLane = (unsigned)(m0 + ((lane >> 3) & 1) * 8 + (lane & 7)) * WPITCH
                       + (unsigned)(lane >> 4) * 16;
  const unsigned pixLane = (unsigned)((lane >> 4) * 8 + (lane & 7)) * XPITCH
                         + (unsigned)((lane >> 3) & 1) * 16;

  float acc[2][8][4];
#pragma unroll
  for (int a = 0; a < 2; a++)
#pragma unroll
    for (int q = 0; q < 8; q++)
#pragma unroll
      for (int r = 0; r < 4; r++) acc[a][q][r] = 0.f;

#pragma unroll 1
  for (int tap = 0; tap < 9; ++tap) {
    const int dy = tap / 3, dx = tap - dy * 3;
    const unsigned bTap = xs_sh + (unsigned)(((wn + dy) * 66) + dx) * XPITCH + pixLane;
    const unsigned aTap = ws_sh + aLane + (unsigned)tap * 64;
#pragma unroll
    for (int cs = 0; cs < 2; ++cs) {
      unsigned a0, a1, a2, a3, a4, a5, a6, a7;
      ldsm_x4(a0, a1, a2, a3, aTap + cs * 32);                 // ch-rows m0..m0+15
      ldsm_x4(a4, a5, a6, a7, aTap + cs * 32 + 16 * WPITCH);   // ch-rows m0+16..m0+31
#pragma unroll
      for (int np = 0; np < 4; ++np) {
        unsigned b0, b1, b2, b3;
        ldsm_x4(b0, b1, b2, b3, bTap + np * 16 * XPITCH + cs * 32);   // 16 pixels
        mma16832(acc[0][2 * np],     a0, a1, a2, a3, b0, b1);
        mma16832(acc[1][2 * np],     a4, a5, a6, a7, b0, b1);
        mma16832(acc[0][2 * np + 1], a0, a1, a2, a3, b2, b3);
        mma16832(acc[1][2 * np + 1], a4, a5, a6, a7, b2, b3);
      }
    }
  }

  const int h = h0 + wn;
#pragma unroll
  for (int mt = 0; mt < 2; ++mt) {
    const int ch0 = m0 + mt * 16 + g;
    const int ch1 = ch0 + 8;
    const float bb0 = b1[ch0], bb1 = b1[ch1];
    const size_t base0 = ((size_t)(n * 64 + ch0) * H_IMG + h) * W_IMG + w0;
    const size_t base1 = ((size_t)(n * 64 + ch1) * H_IMG + h) * W_IMG + w0;
#pragma unroll
    for (int nt = 0; nt < 8; ++nt) {
      const int w = nt * 8 + 2 * tg;
      float v0 = fmaxf(acc[mt][nt][0] + bb0, 0.f);
      float v1 = fmaxf(acc[mt][nt][1] + bb0, 0.f);
      float v2 = fmaxf(acc[mt][nt][2] + bb1, 0.f);
      float v3 = fmaxf(acc[mt][nt][3] + bb1, 0.f);
      *(unsigned short*)&g_h1[base0 + w] =
        (unsigned short)__nv_cvt_float2_to_fp8x2(make_float2(v0, v1), __NV_SATFINITE, __NV_E4M3);
      *(unsigned short*)&g_h1[base1 + w] =
        (unsigned short)__nv_cvt_float2_to_fp8x2(make_float2(v2, v3), __NV_SATFINITE, __NV_E4M3);
    }
  }
}

// ===== conv2 (64->32 3x3 SAME + ReLU) fused with conv3 (1x1) -> fp32 logits =====
__global__ __launch_bounds__(512) void conv2_kernel(
    const float* __restrict__ w2, const float* __restrict__ b2,
    const float* __restrict__ w3, const float* __restrict__ b3) {
  extern __shared__ char smem[];
  unsigned char* xs = (unsigned char*)smem;
  unsigned char* ws = (unsigned char*)(smem + XS_BYTES);
  const int tid = threadIdx.x;
  const int n  = blockIdx.z;
  const int h0 = blockIdx.y * 8;
  const int w0 = blockIdx.x * 64;

  for (int i = tid; i < 32 * 576; i += 512) {
    int m = i / 576, rem = i - m * 576;
    int c = rem / 9, tap = rem - c * 9;
    ws[m * WPITCH + tap * 64 + c] = f2e4m3(w2[i]);
  }
  for (int i = tid; i < 10 * 64 * 66; i += 512) {
    int col = i % 66;
    int t = i / 66;
    int c = t & 63, r = t >> 6;
    int h = h0 - 1 + r, w = w0 - 1 + col;
    unsigned char v = 0;
    if ((unsigned)h < (unsigned)H_IMG && (unsigned)w < (unsigned)W_IMG)
      v = g_h1[((size_t)(n * 64 + c) * H_IMG + h) * W_IMG + w];
    xs[(r * 66 + col) * XPITCH + c] = v;
  }
  __syncthreads();

  const int lane = tid & 31, wid = tid >> 5;
  const int g = lane >> 2, tg = lane & 3;
  const int wn = wid & 7;
  const int wh = wid >> 3;   // pixel half

  const unsigned ws_sh = (unsigned)__cvta_generic_to_shared(ws);
  const unsigned xs_sh = (unsigned)__cvta_generic_to_shared(xs);
  const unsigned aLane = (unsigned)(((lane >> 3) & 1) * 8 + (lane & 7)) * WPITCH
                       + (unsigned)(lane >> 4) * 16;
  const unsigned pixLane = (unsigned)((lane >> 4) * 8 + (lane & 7)) * XPITCH
                         + (unsigned)((lane >> 3) & 1) * 16;

  float acc[2][4][4];
#pragma unroll
  for (int a = 0; a < 2; a++)
#pragma unroll
    for (int q = 0; q < 4; q++)
#pragma unroll
      for (int r = 0; r < 4; r++) acc[a][q][r] = 0.f;

#pragma unroll 1
  for (int tap = 0; tap < 9; ++tap) {
    const int dy = tap / 3, dx = tap - dy * 3;
    const unsigned bTap = xs_sh + (unsigned)(((wn + dy) * 66) + wh * 32 + dx) * XPITCH + pixLane;
    const unsigned aTap = ws_sh + aLane + (unsigned)tap * 64;
#pragma unroll
    for (int cs = 0; cs < 2; ++cs) {
      unsigned a0, a1, a2, a3, a4, a5, a6, a7;
      ldsm_x4(a0, a1, a2, a3, aTap + cs * 32);                 // ch 0..15
      ldsm_x4(a4, a5, a6, a7, aTap + cs * 32 + 16 * WPITCH);   // ch 16..31
#pragma unroll
      for (int np = 0; np < 2; ++np) {
        unsigned b0, b1, b2, b3;
        ldsm_x4(b0, b1, b2, b3, bTap + np * 16 * XPITCH + cs * 32);
        mma16832(acc[0][2 * np],     a0, a1, a2, a3, b0, b1);
        mma16832(acc[1][2 * np],     a4, a5, a6, a7, b0, b1);
        mma16832(acc[0][2 * np + 1], a0, a1, a2, a3, b2, b3);
        mma16832(acc[1][2 * np + 1], a4, a5, a6, a7, b2, b3);
      }
    }
  }

  // epilogue: logit = sum_ch relu(h2+b2)*w3 + b3 ; lane channels {g, g+8, g+16, g+24}
  const float w3v0 = w3[g],      w3v1 = w3[g + 8];
  const float w3v2 = w3[g + 16], w3v3 = w3[g + 24];
  const float b2v0 = b2[g],      b2v1 = b2[g + 8];
  const float b2v2 = b2[g + 16], b2v3 = b2[g + 24];
  const float b3v = b3[0];
  const int h = h0 + wn;
  float* heat = g_heat + (size_t)n * NPIX + (size_t)h * W_IMG + w0 + wh * 32;
#pragma unroll
  for (int nt = 0; nt < 4; ++nt) {
    float s0 = fmaxf(acc[0][nt][0] + b2v0, 0.f) * w3v0
             + fmaxf(acc[0][nt][2] + b2v1, 0.f) * w3v1
             + fmaxf(acc[1][nt][0] + b2v2, 0.f) * w3v2
             + fmaxf(acc[1][nt][2] + b2v3, 0.f) * w3v3;
    float s1 = fmaxf(acc[0][nt][1] + b2v0, 0.f) * w3v0
             + fmaxf(acc[0][nt][3] + b2v1, 0.f) * w3v1
             + fmaxf(acc[1][nt][1] + b2v2, 0.f) * w3v2
             + fmaxf(acc[1][nt][3] + b2v3, 0.f) * w3v3;
#pragma unroll
    for (int off = 4; off < 32; off <<= 1) {
      s0 += __shfl_xor_sync(0xffffffffu, s0, off);
      s1 += __shfl_xor_sync(0xffffffffu, s1, off);
    }
    if (g == 0) {
      heat[nt * 8 + 2 * tg]     = s0 + b3v;
      heat[nt * 8 + 2 * tg + 1] = s1 + b3v;
    }
  }
}

// ============== candidate top-32 per image (approx logits) ==============
__global__ __launch_bounds__(1024) void cand_kernel() {
  __shared__ float sv[3072];
  __shared__ int   si[3072];
  const int n = blockIdx.x;
  const int tid = threadIdx.x;
  const float* heat = g_heat + (size_t)n * NPIX;
  float v0 = -FLT_MAX, v1 = -FLT_MAX, v2 = -FLT_MAX;
  int i0 = 0x7fffffff, i1 = 0x7fffffff, i2 = 0x7fffffff;
  for (int i = tid; i < NPIX; i += 1024) {
    float v = heat[i];
    if (v > v0)      { v2 = v1; i2 = i1; v1 = v0; i1 = i0; v0 = v; i0 = i; }
    else if (v > v1) { v2 = v1; i2 = i1; v1 = v; i1 = i; }
    else if (v > v2) { v2 = v; i2 = i; }
  }
  sv[tid * 3] = v0;     si[tid * 3] = i0;
  sv[tid * 3 + 1] = v1; si[tid * 3 + 1] = i1;
  sv[tid * 3 + 2] = v2; si[tid * 3 + 2] = i2;
  __syncthreads();
  if (tid == 0) {
    float bv[NCAND]; int bi[NCAND];
#pragma unroll
    for (int j = 0; j < NCAND; j++) { bv[j] = -FLT_MAX; bi[j] = 0x7fffffff; }
    for (int e = 0; e < 3072; e++) {
      float v = sv[e]; int id = si[e];
      if (v > bv[NCAND - 1] || (v == bv[NCAND - 1] && id < bi[NCAND - 1])) {
        int j = NCAND - 1;
        while (j > 0 && (v > bv[j - 1] || (v == bv[j - 1] && id < bi[j - 1]))) {
          bv[j] = bv[j - 1]; bi[j] = bi[j - 1]; j--;
        }
        bv[j] = v; bi[j] = id;
      }
    }
    for (int j = 0; j < NCAND; j++) g_cand[n * NCAND + j] = bi[j];
  }
}

// ============== exact fp32 refinement of candidate logits ==============
__global__ __launch_bounds__(288) void refine_kernel(
    const float* __restrict__ x,
    const float* __restrict__ w1, const float* __restrict__ b1,
    const float* __restrict__ w2, const float* __restrict__ b2,
    const float* __restrict__ w3, const float* __restrict__ b3) {
  extern __shared__ float rs[];
  float* ws1  = rs + ROFF_WS1;   // [64][577]
  float* xp   = rs + ROFF_XP;    // [64][28]
  float* h1p  = rs + ROFF_H1;    // [9][65]
  float* part = rs + ROFF_PART;  // [32][9]
  float* s2   = rs + ROFF_S2;    // [32]
  const int cand = blockIdx.x;
  const int n = cand / NCAND;
  const int tid = threadIdx.x;
  const int pix = g_cand[cand];
  const int hc = pix / W_IMG, wc = pix % W_IMG;

  for (int i = tid; i < 64 * 576; i += 288) {
    int c = i / 576, j = i - c * 576;
    ws1[c * 577 + j] = w1[i];
  }
  for (int i = tid; i < 64 * 25; i += 288) {
    int c = i / 25, p = i - c * 25;
    int y = hc - 2 + p / 5, w = wc - 2 + p % 5;
    float v = 0.f;
    if ((unsigned)y < (unsigned)H_IMG && (unsigned)w < (unsigned)W_IMG)
      v = x[((size_t)(n * C_IN + c) * H_IMG + y) * W_IMG + w];
    xp[c * 28 + p] = v;
  }
  __syncthreads();

  for (int i = tid; i < 576; i += 288) {
    int pos = i >> 6, c = i & 63;
    int py = pos / 3, px = pos - py * 3;
    int yy = hc - 1 + py, xx = wc - 1 + px;
    float s = 0.f;
    if ((unsigned)yy < (unsigned)H_IMG && (unsigned)xx < (unsigned)W_IMG) {
      const float* wrow = ws1 + c * 577;
      for (int ic = 0; ic < 64; ic++) {
#pragma unroll
        for (int ty = 0; ty < 3; ty++)
#pragma unroll
          for (int tx = 0; tx < 3; tx++)
            s += xp[ic * 28 + (py + ty) * 5 + (px + tx)] * wrow[ic * 9 + ty * 3 + tx];
      }
      s = fmaxf(s + b1[c], 0.f);
    }
    h1p[pos * 65 + c] = s;
  }
  __syncthreads();

  {
    int ch = tid / 9, pos = tid - ch * 9;
    float s = 0.f;
    const float* wrow = w2 + (size_t)ch * 576;
    for (int ic = 0; ic < 64; ic++)
      s += h1p[pos * 65 + ic] * wrow[ic * 9 + pos];
    part[ch * 9 + pos] = s;
  }
  __syncthreads();
  if (tid < 32) {
    float s = 0.f;
#pragma unroll
    for (int p = 0; p < 9; p++) s += part[tid * 9 + p];
    s2[tid] = fmaxf(s + b2[tid], 0.f) * w3[tid];
  }
  __syncthreads();
  if (tid == 0) {
    float t = b3[0];
    for (int j = 0; j < 32; j++) t += s2[j];
    g_rlogit[cand] = t;
  }
}

// ============== final: top-2 per image from refined logits -> rois ==============
__global__ __launch_bounds__(96) void final_kernel(float* __restrict__ out) {
  __shared__ float hc_s[B_IMG * K_ROIS], wc_s[B_IMG * K_ROIS];
  const int tid = threadIdx.x;
  if (tid < B_IMG) {
    float v1 = -FLT_MAX, v2 = -FLT_MAX;
    int p1 = 0x7fffffff, p2 = 0x7fffffff;
    for (int j = 0; j < NCAND; j++) {
      float v = g_rlogit[tid * NCAND + j];
      int p = g_cand[tid * NCAND + j];
      if (v > v1 || (v == v1 && p < p1)) { v2 = v1; p2 = p1; v1 = v; p1 = p; }
      else if (v > v2 || (v == v2 && p < p2)) { v2 = v; p2 = p; }
    }
    hc_s[tid * 2]     = (float)(p1 / W_IMG);
    wc_s[tid * 2]     = (float)(p1 % W_IMG);
    hc_s[tid * 2 + 1] = (float)(p2 / W_IMG);
    wc_s[tid * 2 + 1] = (float)(p2 % W_IMG);
  }
  __syncthreads();
  for (int i = tid; i < NUM_FRAMES * B_IMG * K_ROIS * 4; i += 96) {
    int f = i / (B_IMG * K_ROIS * 4);
    int rem = i - f * (B_IMG * K_ROIS * 4);
    int j = rem >> 2, comp = rem & 3;
    float val;
    if (comp == 0)      val = (float)(j >> 1);
    else if (comp == 1) val = (float)f;
    else if (comp == 2) val = hc_s[j];
    else                val = wc_s[j];
    out[i] = val;
  }
}

// ---------------- launch ----------------
extern "C" void kernel_launch(void* const* d_in, const int* in_sizes, int n_in,
                              void* d_out, int out_size) {
  const float* x  = (const float*)d_in[0];
  const float* w1 = (const float*)d_in[1];
  const float* b1 = (const float*)d_in[2];
  const float* w2 = (const float*)d_in[3];
  const float* b2 = (const float*)d_in[4];
  const float* w3 = (const float*)d_in[5];
  const float* b3 = (const float*)d_in[6];
  float* out = (float*)d_out;

  cudaFuncSetAttribute(conv1_kernel, cudaFuncAttributeMaxDynamicSharedMemorySize, SMEM1);
  cudaFuncSetAttribute(conv2_kernel, cudaFuncAttributeMaxDynamicSharedMemorySize, SMEM2);
  cudaFuncSetAttribute(refine_kernel, cudaFuncAttributeMaxDynamicSharedMemorySize, RSMEM_BYTES);

  conv1_kernel<<<dim3(8, 36, 8), 512, SMEM1>>>(x, w1, b1);
  conv2_kernel<<<dim3(8, 36, 8), 512, SMEM2>>>(w2, b2, w3, b3);
  cand_kernel<<<8, 1024>>>();
  refine_kernel<<<B_IMG * NCAND, 288, RSMEM_BYTES>>>(x, w1, b1, w2, b2, w3, b3);
  final_kernel<<<1, 96>>>(out);
}

// round 11
// speedup vs baseline: 1.3085x; 1.3085x over previous
#include <cuda_runtime.h>
#include <cuda_bf16.h>
#include <float.h>

#define B_IMG 8
#define C_IN 64
#define H_IMG 288
#define W_IMG 512
#define NPIX (H_IMG * W_IMG)
#define NUM_FRAMES 9
#define K_ROIS 2
#define NCAND 16

// ---------------- scratch (device globals; no allocation allowed) ----------------
__device__ __align__(16) __nv_bfloat16 g_xb[(size_t)B_IMG * 64 * H_IMG * W_IMG];  // bf16 x, 151 MB
__device__ __align__(16) __nv_bfloat16 g_h1[(size_t)B_IMG * 64 * H_IMG * W_IMG];  // bf16 h1, 151 MB
__device__ __align__(16) __nv_bfloat16 g_w1b[64 * 584];   // pitched, smem-ready
__device__ __align__(16) __nv_bfloat16 g_w2b[32 * 584];
__device__ __align__(16) float g_heat[(size_t)B_IMG * NPIX];
__device__ int   g_cand[B_IMG * NCAND];
__device__ float g_rlogit[B_IMG * NCAND];

// ---------------- mma.sync bf16 m16n8k16, row.col, fp32 accum ----------------
__device__ __forceinline__ void mma16816(float* d,
    unsigned a0, unsigned a1, unsigned a2, unsigned a3, unsigned b0, unsigned b1) {
  asm volatile(
    "mma.sync.aligned.m16n8k16.row.col.f32.bf16.bf16.f32 "
    "{%0,%1,%2,%3}, {%4,%5,%6,%7}, {%8,%9}, {%0,%1,%2,%3};\n"
    : "+f"(d[0]), "+f"(d[1]), "+f"(d[2]), "+f"(d[3])
    : "r"(a0), "r"(a1), "r"(a2), "r"(a3), "r"(b0), "r"(b1));
}

__device__ __forceinline__ void ldsm_x4(unsigned& r0, unsigned& r1, unsigned& r2, unsigned& r3,
                                        unsigned addr) {
  asm volatile("ldmatrix.sync.aligned.m8n8.x4.shared.b16 {%0,%1,%2,%3}, [%4];\n"
    : "=r"(r0), "=r"(r1), "=r"(r2), "=r"(r3) : "r"(addr));
}

// smem geometry: 8-row tiles => 10-row strips (bf16)
// xs: [(r*66+col)][72 ch] -> pixel stride 144 B (16B aligned; conflict-free ldmatrix)
// ws: [m][584] -> row stride 1168 B (16B aligned; conflict-free)
#define XS_BYTES (10 * 66 * 72 * 2)     // 95040
#define WS1_BYTES (64 * 584 * 2)        // 74752
#define SMEM1 (XS_BYTES + WS1_BYTES)    // 169792
#define WS2_BYTES (32 * 584 * 2)        // 37376
#define SMEM2 (XS_BYTES + WS2_BYTES)    // 132416

// refine smem layout (floats)
#define ROFF_WS1 0                       // 64*577
#define ROFF_XP  (64 * 577)              // 64*28
#define ROFF_H1  (ROFF_XP + 64 * 28)     // 9*65
#define ROFF_PART (ROFF_H1 + 9 * 65)     // 32*9
#define ROFF_S2  (ROFF_PART + 32 * 9)    // 32
#define RSMEM_FLOATS (ROFF_S2 + 32)
#define RSMEM_BYTES (RSMEM_FLOATS * 4)   // ~158.5 KB

// ================= prep: one-time per-launch conversions =================
__global__ __launch_bounds__(512) void prep_x_kernel(const float* __restrict__ x) {
  const size_t total4 = (size_t)B_IMG * 64 * H_IMG * W_IMG / 4;
  const float4* src = (const float4*)x;
  uint2* dst = (uint2*)g_xb;
  for (size_t i = (size_t)blockIdx.x * blockDim.x + threadIdx.x; i < total4;
       i += (size_t)gridDim.x * blockDim.x) {
    float4 v = src[i];
    __nv_bfloat162 p0 = __floats2bfloat162_rn(v.x, v.y);
    __nv_bfloat162 p1 = __floats2bfloat162_rn(v.z, v.w);
    uint2 o;
    o.x = *reinterpret_cast<unsigned*>(&p0);
    o.y = *reinterpret_cast<unsigned*>(&p1);
    dst[i] = o;
  }
}

// weights into pitched layout: g_w*b[m*584 + tap*64 + c] = w[m,c,tap]; pads zeroed
__global__ __launch_bounds__(512) void prep_w_kernel(
    const float* __restrict__ w1, const float* __restrict__ w2) {
  const int stride = gridDim.x * blockDim.x;
  const int tid = blockIdx.x * blockDim.x + threadIdx.x;
  for (int i = tid; i < 64 * 584; i += stride) {
    int m = i / 584, j = i - m * 584;
    float v = 0.f;
    if (j < 576) { int tap = j >> 6, c = j & 63; v = w1[m * 576 + c * 9 + tap]; }
    g_w1b[i] = __float2bfloat16(v);
  }
  for (int i = tid; i < 32 * 584; i += stride) {
    int m = i / 584, j = i - m * 584;
    float v = 0.f;
    if (j < 576) { int tap = j >> 6, c = j & 63; v = w2[m * 576 + c * 9 + tap]; }
    g_w2b[i] = __float2bfloat16(v);
  }
}

// ================= conv1: 64->64 3x3 SAME + ReLU, bf16 out =================
// tile: 64 px wide x 8 rows, all 64 out ch. 512 threads / 16 warps.
__global__ __launch_bounds__(512) void conv1_kernel(const float* __restrict__ b1) {
  extern __shared__ char smem[];
  __nv_bfloat16* xs = (__nv_bfloat16*)smem;
  __nv_bfloat16* ws = (__nv_bfloat16*)(smem + XS_BYTES);
  const int tid = threadIdx.x;
  const int n  = blockIdx.z;
  const int h0 = blockIdx.y * 8;
  const int w0 = blockIdx.x * 64;

  // ws: straight vector copy of pre-pitched bf16 weights
  {
    const uint4* src = (const uint4*)g_w1b;
    uint4* dst = (uint4*)ws;
    for (int i = tid; i < WS1_BYTES / 16; i += 512) dst[i] = src[i];
  }
  // xs strip rows h0-1..h0+8, cols w0-1..w0+64 (bf16 copy, no convert)
  for (int i = tid; i < 10 * 64 * 66; i += 512) {
    int col = i % 66;
    int t = i / 66;
    int c = t & 63, r = t >> 6;
    int h = h0 - 1 + r, w = w0 - 1 + col;
    __nv_bfloat16 v = __float2bfloat16(0.f);
    if ((unsigned)h < (unsigned)H_IMG && (unsigned)w < (unsigned)W_IMG)
      v = g_xb[((size_t)(n * C_IN + c) * H_IMG + h) * W_IMG + w];
    xs[(r * 66 + col) * 72 + c] = v;
  }
  __syncthreads();

  const int lane = tid & 31, wid = tid >> 5;
  const int g = lane >> 2, tg = lane & 3;
  const int wn = wid & 7;       // output row 0..7
  const int wh = wid >> 3;      // channel half
  const int m0 = wh * 32;

  const unsigned ws_sh = (unsigned)__cvta_generic_to_shared(ws);
  const unsigned xs_sh = (unsigned)__cvta_generic_to_shared(xs);
  const unsigned aLane = (unsigned)(m0 + ((lane >> 3) & 1) * 8 + (lane & 7)) * 1168
                       + (unsigned)(lane >> 4) * 16;
  const unsigned pixLane = (unsigned)((lane >> 4) * 8 + (lane & 7)) * 144
                         + (unsigned)((lane >> 3) & 1) * 16;

  float acc[2][8][4];
#pragma unroll
  for (int a = 0; a < 2; a++)
#pragma unroll
    for (int q = 0; q < 8; q++)
#pragma unroll
      for (int r = 0; r < 4; r++) acc[a][q][r] = 0.f;

#pragma unroll 1
  for (int tap = 0; tap < 9; ++tap) {
    const int dy = tap / 3, dx = tap - dy * 3;
    const unsigned bTap = xs_sh + (unsigned)(((wn + dy) * 66) + dx) * 144 + pixLane;
    const unsigned aTap = ws_sh + aLane + (unsigned)tap * 128;
#pragma unroll
    for (int cs = 0; cs < 4; ++cs) {
      unsigned a0, a1, a2, a3, a4, a5, a6, a7;
      ldsm_x4(a0, a1, a2, a3, aTap + cs * 32);
      ldsm_x4(a4, a5, a6, a7, aTap + cs * 32 + 18688);   // rows m0+16..m0+31
#pragma unroll
      for (int np = 0; np < 4; ++np) {
        unsigned b0, b1, b2, b3;
        ldsm_x4(b0, b1, b2, b3, bTap + np * 2304 + cs * 32);   // 16 pixels, k0-15
        mma16816(acc[0][2 * np],     a0, a1, a2, a3, b0, b1);
        mma16816(acc[1][2 * np],     a4, a5, a6, a7, b0, b1);
        mma16816(acc[0][2 * np + 1], a0, a1, a2, a3, b2, b3);
        mma16816(acc[1][2 * np + 1], a4, a5, a6, a7, b2, b3);
      }
    }
  }

  const int h = h0 + wn;
#pragma unroll
  for (int mt = 0; mt < 2; ++mt) {
    const int ch0 = m0 + mt * 16 + g;
    const int ch1 = ch0 + 8;
    const float bb0 = b1[ch0], bb1 = b1[ch1];
    const size_t base0 = ((size_t)(n * 64 + ch0) * H_IMG + h) * W_IMG + w0;
    const size_t base1 = ((size_t)(n * 64 + ch1) * H_IMG + h) * W_IMG + w0;
#pragma unroll
    for (int nt = 0; nt < 8; ++nt) {
      const int w = nt * 8 + 2 * tg;
      float v0 = fmaxf(acc[mt][nt][0] + bb0, 0.f);
      float v1 = fmaxf(acc[mt][nt][1] + bb0, 0.f);
      float v2 = fmaxf(acc[mt][nt][2] + bb1, 0.f);
      float v3 = fmaxf(acc[mt][nt][3] + bb1, 0.f);
      *(__nv_bfloat162*)&g_h1[base0 + w] = __floats2bfloat162_rn(v0, v1);
      *(__nv_bfloat162*)&g_h1[base1 + w] = __floats2bfloat162_rn(v2, v3);
    }
  }
}

// ===== conv2 (64->32 3x3 SAME + ReLU) fused with conv3 (1x1) -> fp32 logits =====
__global__ __launch_bounds__(512) void conv2_kernel(
    const float* __restrict__ b2,
    const float* __restrict__ w3, const float* __restrict__ b3) {
  extern __shared__ char smem[];
  __nv_bfloat16* xs = (__nv_bfloat16*)smem;
  __nv_bfloat16* ws = (__nv_bfloat16*)(smem + XS_BYTES);
  const int tid = threadIdx.x;
  const int n  = blockIdx.z;
  const int h0 = blockIdx.y * 8;
  const int w0 = blockIdx.x * 64;

  {
    const uint4* src = (const uint4*)g_w2b;
    uint4* dst = (uint4*)ws;
    for (int i = tid; i < WS2_BYTES / 16; i += 512) dst[i] = src[i];
  }
  for (int i = tid; i < 10 * 64 * 66; i += 512) {
    int col = i % 66;
    int t = i / 66;
    int c = t & 63, r = t >> 6;
    int h = h0 - 1 + r, w = w0 - 1 + col;
    __nv_bfloat16 v = __float2bfloat16(0.f);
    if ((unsigned)h < (unsigned)H_IMG && (unsigned)w < (unsigned)W_IMG)
      v = g_h1[((size_t)(n * 64 + c) * H_IMG + h) * W_IMG + w];
    xs[(r * 66 + col) * 72 + c] = v;
  }
  __syncthreads();

  const int lane = tid & 31, wid = tid >> 5;
  const int g = lane >> 2, tg = lane & 3;
  const int wn = wid & 7;
  const int wh = wid >> 3;   // pixel half

  const unsigned ws_sh = (unsigned)__cvta_generic_to_shared(ws);
  const unsigned xs_sh = (unsigned)__cvta_generic_to_shared(xs);
  const unsigned aLane = (unsigned)(((lane >> 3) & 1) * 8 + (lane & 7)) * 1168
                       + (unsigned)(lane >> 4) * 16;
  const unsigned pixLane = (unsigned)((lane >> 4) * 8 + (lane & 7)) * 144
                         + (unsigned)((lane >> 3) & 1) * 16;

  float acc[2][4][4];
#pragma unroll
  for (int a = 0; a < 2; a++)
#pragma unroll
    for (int q = 0; q < 4; q++)
#pragma unroll
      for (int r = 0; r < 4; r++) acc[a][q][r] = 0.f;

#pragma unroll 1
  for (int tap = 0; tap < 9; ++tap) {
    const int dy = tap / 3, dx = tap - dy * 3;
    const unsigned bTap = xs_sh + (unsigned)(((wn + dy) * 66) + wh * 32 + dx) * 144 + pixLane;
    const unsigned aTap = ws_sh + aLane + (unsigned)tap * 128;
#pragma unroll
    for (int cs = 0; cs < 4; ++cs) {
      unsigned a0, a1, a2, a3, a4, a5, a6, a7;
      ldsm_x4(a0, a1, a2, a3, aTap + cs * 32);            // ch 0..15
      ldsm_x4(a4, a5, a6, a7, aTap + cs * 32 + 18688);    // ch 16..31
#pragma unroll
      for (int np = 0; np < 2; ++np) {
        unsigned b0, b1, b2, b3;
        ldsm_x4(b0, b1, b2, b3, bTap + np * 2304 + cs * 32);
        mma16816(acc[0][2 * np],     a0, a1, a2, a3, b0, b1);
        mma16816(acc[1][2 * np],     a4, a5, a6, a7, b0, b1);
        mma16816(acc[0][2 * np + 1], a0, a1, a2, a3, b2, b3);
        mma16816(acc[1][2 * np + 1], a4, a5, a6, a7, b2, b3);
      }
    }
  }

  // epilogue: logit = sum_ch relu(h2+b2)*w3 + b3 ; lane channels {g, g+8, g+16, g+24}
  const float w3v0 = w3[g],      w3v1 = w3[g + 8];
  const float w3v2 = w3[g + 16], w3v3 = w3[g + 24];
  const float b2v0 = b2[g],      b2v1 = b2[g + 8];
  const float b2v2 = b2[g + 16], b2v3 = b2[g + 24];
  const float b3v = b3[0];
  const int h = h0 + wn;
  float* heat = g_heat + (size_t)n * NPIX + (size_t)h * W_IMG + w0 + wh * 32;
#pragma unroll
  for (int nt = 0; nt < 4; ++nt) {
    float s0 = fmaxf(acc[0][nt][0] + b2v0, 0.f) * w3v0
             + fmaxf(acc[0][nt][2] + b2v1, 0.f) * w3v1
             + fmaxf(acc[1][nt][0] + b2v2, 0.f) * w3v2
             + fmaxf(acc[1][nt][2] + b2v3, 0.f) * w3v3;
    float s1 = fmaxf(acc[0][nt][1] + b2v0, 0.f) * w3v0
             + fmaxf(acc[0][nt][3] + b2v1, 0.f) * w3v1
             + fmaxf(acc[1][nt][1] + b2v2, 0.f) * w3v2
             + fmaxf(acc[1][nt][3] + b2v3, 0.f) * w3v3;
#pragma unroll
    for (int off = 4; off < 32; off <<= 1) {
      s0 += __shfl_xor_sync(0xffffffffu, s0, off);
      s1 += __shfl_xor_sync(0xffffffffu, s1, off);
    }
    if (g == 0) {
      heat[nt * 8 + 2 * tg]     = s0 + b3v;
      heat[nt * 8 + 2 * tg + 1] = s1 + b3v;
    }
  }
}

// ============== candidate top-16 per image (approx logits) ==============
__global__ __launch_bounds__(1024) void cand_kernel() {
  __shared__ float sv[2048];
  __shared__ int   si[2048];
  const int n = blockIdx.x;
  const int tid = threadIdx.x;
  const float* heat = g_heat + (size_t)n * NPIX;
  float v0 = -FLT_MAX, v1 = -FLT_MAX;
  int i0 = 0x7fffffff, i1 = 0x7fffffff;
  for (int i = tid; i < NPIX; i += 1024) {
    float v = heat[i];
    if (v > v0) { v1 = v0; i1 = i0; v0 = v; i0 = i; }
    else if (v > v1) { v1 = v; i1 = i; }
  }
  sv[tid * 2] = v0; si[tid * 2] = i0;
  sv[tid * 2 + 1] = v1; si[tid * 2 + 1] = i1;
  __syncthreads();
  if (tid == 0) {
    float bv[NCAND]; int bi[NCAND];
#pragma unroll
    for (int j = 0; j < NCAND; j++) { bv[j] = -FLT_MAX; bi[j] = 0x7fffffff; }
    for (int e = 0; e < 2048; e++) {
      float v = sv[e]; int id = si[e];
      if (v > bv[NCAND - 1] || (v == bv[NCAND - 1] && id < bi[NCAND - 1])) {
        int j = NCAND - 1;
        while (j > 0 && (v > bv[j - 1] || (v == bv[j - 1] && id < bi[j - 1]))) {
          bv[j] = bv[j - 1]; bi[j] = bi[j - 1]; j--;
        }
        bv[j] = v; bi[j] = id;
      }
    }
    for (int j = 0; j < NCAND; j++) g_cand[n * NCAND + j] = bi[j];
  }
}

// ============== exact fp32 refinement of candidate logits ==============
__global__ __launch_bounds__(288) void refine_kernel(
    const float* __restrict__ x,
    const float* __restrict__ w1, const float* __restrict__ b1,
    const float* __restrict__ w2, const float* __restrict__ b2,
    const float* __restrict__ w3, const float* __restrict__ b3) {
  extern __shared__ float rs[];
  float* ws1  = rs + ROFF_WS1;   // [64][577]
  float* xp   = rs + ROFF_XP;    // [64][28]
  float* h1p  = rs + ROFF_H1;    // [9][65]
  float* part = rs + ROFF_PART;  // [32][9]
  float* s2   = rs + ROFF_S2;    // [32]
  const int cand = blockIdx.x;
  const int n = cand / NCAND;
  const int tid = threadIdx.x;
  const int pix = g_cand[cand];
  const int hc = pix / W_IMG, wc = pix % W_IMG;

  for (int i = tid; i < 64 * 576; i += 288) {
    int c = i / 576, j = i - c * 576;
    ws1[c * 577 + j] = w1[i];
  }
  for (int i = tid; i < 64 * 25; i += 288) {
    int c = i / 25, p = i - c * 25;
    int y = hc - 2 + p / 5, w = wc - 2 + p % 5;
    float v = 0.f;
    if ((unsigned)y < (unsigned)H_IMG && (unsigned)w < (unsigned)W_IMG)
      v = x[((size_t)(n * C_IN + c) * H_IMG + y) * W_IMG + w];
    xp[c * 28 + p] = v;
  }
  __syncthreads();

  for (int i = tid; i < 576; i += 288) {
    int pos = i >> 6, c = i & 63;
    int py = pos / 3, px = pos - py * 3;
    int yy = hc - 1 + py, xx = wc - 1 + px;
    float s = 0.f;
    if ((unsigned)yy < (unsigned)H_IMG && (unsigned)xx < (unsigned)W_IMG) {
      const float* wrow = ws1 + c * 577;
      for (int ic = 0; ic < 64; ic++) {
#pragma unroll
        for (int ty = 0; ty < 3; ty++)
#pragma unroll
          for (int tx = 0; tx < 3; tx++)
            s += xp[ic * 28 + (py + ty) * 5 + (px + tx)] * wrow[ic * 9 + ty * 3 + tx];
      }
      s = fmaxf(s + b1[c], 0.f);
    }
    h1p[pos * 65 + c] = s;
  }
  __syncthreads();

  {
    int ch = tid / 9, pos = tid - ch * 9;
    float s = 0.f;
    const float* wrow = w2 + (size_t)ch * 576;
    for (int ic = 0; ic < 64; ic++)
      s += h1p[pos * 65 + ic] * wrow[ic * 9 + pos];
    part[ch * 9 + pos] = s;
  }
  __syncthreads();
  if (tid < 32) {
    float s = 0.f;
#pragma unroll
    for (int p = 0; p < 9; p++) s += part[tid * 9 + p];
    s2[tid] = fmaxf(s + b2[tid], 0.f) * w3[tid];
  }
  __syncthreads();
  if (tid == 0) {
    float t = b3[0];
    for (int j = 0; j < 32; j++) t += s2[j];
    g_rlogit[cand] = t;
  }
}

// ============== final: top-2 per image from refined logits -> rois ==============
__global__ __launch_bounds__(96) void final_kernel(float* __restrict__ out) {
  __shared__ float hc_s[B_IMG * K_ROIS], wc_s[B_IMG * K_ROIS];
  const int tid = threadIdx.x;
  if (tid < B_IMG) {
    float v1 = -FLT_MAX, v2 = -FLT_MAX;
    int p1 = 0x7fffffff, p2 = 0x7fffffff;
    for (int j = 0; j < NCAND; j++) {
      float v = g_rlogit[tid * NCAND + j];
      int p = g_cand[tid * NCAND + j];
      if (v > v1 || (v == v1 && p < p1)) { v2 = v1; p2 = p1; v1 = v; p1 = p; }
      else if (v > v2 || (v == v2 && p < p2)) { v2 = v; p2 = p; }
    }
    hc_s[tid * 2]     = (float)(p1 / W_IMG);
    wc_s[tid * 2]     = (float)(p1 % W_IMG);
    hc_s[tid * 2 + 1] = (float)(p2 / W_IMG);
    wc_s[tid * 2 + 1] = (float)(p2 % W_IMG);
  }
  __syncthreads();
  for (int i = tid; i < NUM_FRAMES * B_IMG * K_ROIS * 4; i += 96) {
    int f = i / (B_IMG * K_ROIS * 4);
    int rem = i - f * (B_IMG * K_ROIS * 4);
    int j = rem >> 2, comp = rem & 3;
    float val;
    if (comp == 0)      val = (float)(j >> 1);
    else if (comp == 1) val = (float)f;
    else if (comp == 2) val = hc_s[j];
    else                val = wc_s[j];
    out[i] = val;
  }
}

// ---------------- launch ----------------
extern "C" void kernel_launch(void* const* d_in, const int* in_sizes, int n_in,
                              void* d_out, int out_size) {
  const float* x  = (const float*)d_in[0];
  const float* w1 = (const float*)d_in[1];
  const float* b1 = (const float*)d_in[2];
  const float* w2 = (const float*)d_in[3];
  const float* b2 = (const float*)d_in[4];
  const float* w3 = (const float*)d_in[5];
  const float* b3 = (const float*)d_in[6];
  float* out = (float*)d_out;

  cudaFuncSetAttribute(conv1_kernel, cudaFuncAttributeMaxDynamicSharedMemorySize, SMEM1);
  cudaFuncSetAttribute(conv2_kernel, cudaFuncAttributeMaxDynamicSharedMemorySize, SMEM2);
  cudaFuncSetAttribute(refine_kernel, cudaFuncAttributeMaxDynamicSharedMemorySize, RSMEM_BYTES);

  prep_x_kernel<<<2048, 512>>>(x);
  prep_w_kernel<<<64, 512>>>(w1, w2);
  conv1_kernel<<<dim3(8, 36, 8), 512, SMEM1>>>(b1);
  conv2_kernel<<<dim3(8, 36, 8), 512, SMEM2>>>(b2, w3, b3);
  cand_kernel<<<8, 1024>>>();
  refine_kernel<<<B_IMG * NCAND, 288, RSMEM_BYTES>>>(x, w1, b1, w2, b2, w3, b3);
  final_kernel<<<1, 96>>>(out);
}

// round 12
// speedup vs baseline: 1.6706x; 1.2768x over previous
#include <cuda_runtime.h>
#include <cuda_bf16.h>
#include <float.h>

#define B_IMG 8
#define C_IN 64
#define H_IMG 288
#define W_IMG 512
#define NPIX (H_IMG * W_IMG)
#define NUM_FRAMES 9
#define K_ROIS 2
#define NCAND 16

// ---------------- scratch (device globals; no allocation allowed) ----------------
// NHWC bf16: element ((n*H + h)*W + w)*64 + c  (128 B per pixel)
__device__ __align__(16) __nv_bfloat16 g_xb[(size_t)B_IMG * H_IMG * W_IMG * 64];  // 151 MB
__device__ __align__(16) __nv_bfloat16 g_h1[(size_t)B_IMG * H_IMG * W_IMG * 64];  // 151 MB
__device__ __align__(16) __nv_bfloat16 g_w1b[64 * 584];   // pitched, smem-ready
__device__ __align__(16) __nv_bfloat16 g_w2b[32 * 584];
__device__ __align__(16) float g_heat[(size_t)B_IMG * NPIX];
__device__ int   g_cand[B_IMG * NCAND];
__device__ float g_rlogit[B_IMG * NCAND];

// ---------------- mma.sync bf16 m16n8k16, row.col, fp32 accum ----------------
__device__ __forceinline__ void mma16816(float* d,
    unsigned a0, unsigned a1, unsigned a2, unsigned a3, unsigned b0, unsigned b1) {
  asm volatile(
    "mma.sync.aligned.m16n8k16.row.col.f32.bf16.bf16.f32 "
    "{%0,%1,%2,%3}, {%4,%5,%6,%7}, {%8,%9}, {%0,%1,%2,%3};\n"
    : "+f"(d[0]), "+f"(d[1]), "+f"(d[2]), "+f"(d[3])
    : "r"(a0), "r"(a1), "r"(a2), "r"(a3), "r"(b0), "r"(b1));
}

__device__ __forceinline__ void ldsm_x4(unsigned& r0, unsigned& r1, unsigned& r2, unsigned& r3,
                                        unsigned addr) {
  asm volatile("ldmatrix.sync.aligned.m8n8.x4.shared.b16 {%0,%1,%2,%3}, [%4];\n"
    : "=r"(r0), "=r"(r1), "=r"(r2), "=r"(r3) : "r"(addr));
}

// smem geometry: xs [(r*66+col)][72 ch] -> pixel stride 144 B; ws [m][584] -> 1168 B
#define XS_BYTES (10 * 66 * 72 * 2)     // 95040
#define WS1_BYTES (64 * 584 * 2)        // 74752
#define SMEM1 (XS_BYTES + WS1_BYTES)    // 169792
#define WS2_BYTES (32 * 584 * 2)        // 37376
#define SMEM2 (XS_BYTES + WS2_BYTES)    // 132416

// refine smem layout (floats)
#define ROFF_WS1 0
#define ROFF_XP  (64 * 577)
#define ROFF_H1  (ROFF_XP + 64 * 28)
#define ROFF_PART (ROFF_H1 + 9 * 65)
#define ROFF_S2  (ROFF_PART + 32 * 9)
#define RSMEM_FLOATS (ROFF_S2 + 32)
#define RSMEM_BYTES (RSMEM_FLOATS * 4)   // ~158.5 KB

// ================= prep: fp32 NCHW -> bf16 NHWC (smem tile transpose) =================
__global__ __launch_bounds__(256) void prep_x_kernel(const float* __restrict__ x) {
  __shared__ __align__(16) __nv_bfloat16 s[64 * 72];
  const int n = blockIdx.z, h = blockIdx.y, wt = blockIdx.x * 64;
  const int tid = threadIdx.x;
  const int w = tid & 63, c0 = tid >> 6;
#pragma unroll
  for (int k = 0; k < 16; k++) {
    int c = c0 + k * 4;
    float v = x[(((size_t)(n * 64 + c) * H_IMG + h) * W_IMG) + wt + w];
    s[w * 72 + c] = __float2bfloat16(v);
  }
  __syncthreads();
  const size_t rowbase = ((size_t)(n * H_IMG + h) * W_IMG + wt) * 64;
#pragma unroll
  for (int i = tid; i < 512; i += 256) {
    int pix = i >> 3, seg = i & 7;
    *(uint4*)&g_xb[rowbase + (size_t)pix * 64 + seg * 8] =
        *(const uint4*)((const char*)s + pix * 144 + seg * 16);
  }
}

// weights into pitched layout: g_w*b[m*584 + tap*64 + c] = w[m,c,tap]; pads zeroed
__global__ __launch_bounds__(512) void prep_w_kernel(
    const float* __restrict__ w1, const float* __restrict__ w2) {
  const int stride = gridDim.x * blockDim.x;
  const int tid = blockIdx.x * blockDim.x + threadIdx.x;
  for (int i = tid; i < 64 * 584; i += stride) {
    int m = i / 584, j = i - m * 584;
    float v = 0.f;
    if (j < 576) { int tap = j >> 6, c = j & 63; v = w1[m * 576 + c * 9 + tap]; }
    g_w1b[i] = __float2bfloat16(v);
  }
  for (int i = tid; i < 32 * 584; i += stride) {
    int m = i / 584, j = i - m * 584;
    float v = 0.f;
    if (j < 576) { int tap = j >> 6, c = j & 63; v = w2[m * 576 + c * 9 + tap]; }
    g_w2b[i] = __float2bfloat16(v);
  }
}

// ================= conv1: 64->64 3x3 SAME + ReLU, NHWC bf16 out =================
// tile 64 px x 8 rows x 64 ch; 16 warps; warp = 64 px (M) x 32 ch (N).
__global__ __launch_bounds__(512) void conv1_kernel(const float* __restrict__ b1) {
  extern __shared__ char smem[];
  __nv_bfloat16* xs = (__nv_bfloat16*)smem;
  __nv_bfloat16* ws = (__nv_bfloat16*)(smem + XS_BYTES);
  const int tid = threadIdx.x;
  const int n  = blockIdx.z;
  const int h0 = blockIdx.y * 8;
  const int w0 = blockIdx.x * 64;

  {
    const uint4* src = (const uint4*)g_w1b;
    uint4* dst = (uint4*)ws;
    for (int i = tid; i < WS1_BYTES / 16; i += 512) dst[i] = src[i];
  }
  // xs strip: 10 rows x 66 cols, NHWC vectorized (8x uint4 per pixel)
  for (int i = tid; i < 5280; i += 512) {
    int pix = i >> 3, seg = i & 7;
    int r = pix / 66, col = pix - r * 66;
    int h = h0 - 1 + r, w = w0 - 1 + col;
    uint4 v = make_uint4(0u, 0u, 0u, 0u);
    if ((unsigned)h < (unsigned)H_IMG && (unsigned)w < (unsigned)W_IMG)
      v = *(const uint4*)&g_xb[((size_t)(n * H_IMG + h) * W_IMG + w) * 64 + seg * 8];
    *(uint4*)((char*)xs + pix * 144 + seg * 16) = v;
  }
  __syncthreads();

  const int lane = tid & 31, wid = tid >> 5;
  const int g = lane >> 2, tg = lane & 3;
  const int wn = wid & 7;       // output row 0..7
  const int wh = wid >> 3;      // channel half
  const int m0 = wh * 32;

  const unsigned ws_sh = (unsigned)__cvta_generic_to_shared(ws);
  const unsigned xs_sh = (unsigned)__cvta_generic_to_shared(xs);
  // A from xs (pixel rows), B from ws (channel rows) — swapped orientation
  const unsigned aLaneX = (unsigned)(((lane >> 3) & 1) * 8 + (lane & 7)) * 144
                        + (unsigned)(lane >> 4) * 16;
  const unsigned wLaneB = (unsigned)((lane >> 4) * 8 + (lane & 7)) * 1168
                        + (unsigned)((lane >> 3) & 1) * 16;

  float acc[4][4][4];
#pragma unroll
  for (int a = 0; a < 4; a++)
#pragma unroll
    for (int q = 0; q < 4; q++)
#pragma unroll
      for (int r = 0; r < 4; r++) acc[a][q][r] = 0.f;

#pragma unroll 1
  for (int tap = 0; tap < 9; ++tap) {
    const int dy = tap / 3, dx = tap - dy * 3;
    const unsigned aTap = xs_sh + (unsigned)(((wn + dy) * 66) + dx) * 144 + aLaneX;
    const unsigned bTap = ws_sh + (unsigned)m0 * 1168 + (unsigned)tap * 128 + wLaneB;
#pragma unroll
    for (int cs = 0; cs < 4; ++cs) {
      unsigned b0, b1r, b2, b3, b4, b5, b6, b7;
      ldsm_x4(b0, b1r, b2, b3, bTap + cs * 32);              // ch m0+0..15
      ldsm_x4(b4, b5, b6, b7, bTap + cs * 32 + 16 * 1168);   // ch m0+16..31
#pragma unroll
      for (int np = 0; np < 4; ++np) {
        unsigned a0, a1, a2, a3;
        ldsm_x4(a0, a1, a2, a3, aTap + np * 2304 + cs * 32); // 16 pixels
        mma16816(acc[np][0], a0, a1, a2, a3, b0, b1r);
        mma16816(acc[np][1], a0, a1, a2, a3, b2, b3);
        mma16816(acc[np][2], a0, a1, a2, a3, b4, b5);
        mma16816(acc[np][3], a0, a1, a2, a3, b6, b7);
      }
    }
  }

  // epilogue: thread holds pixels {np*16+g, +8}, channels {m0+q*8+2tg, +1} -> bf162 NHWC
  const int h = h0 + wn;
  const size_t rowbase = ((size_t)(n * H_IMG + h) * W_IMG + w0) * 64;
#pragma unroll
  for (int q = 0; q < 4; ++q) {
    const int ch = m0 + q * 8 + 2 * tg;
    const float bb0 = b1[ch], bb1 = b1[ch + 1];
#pragma unroll
    for (int np = 0; np < 4; ++np) {
      const int p0 = np * 16 + g;
      float v0 = fmaxf(acc[np][q][0] + bb0, 0.f);
      float v1 = fmaxf(acc[np][q][1] + bb1, 0.f);
      float v2 = fmaxf(acc[np][q][2] + bb0, 0.f);
      float v3 = fmaxf(acc[np][q][3] + bb1, 0.f);
      *(__nv_bfloat162*)&g_h1[rowbase + (size_t)p0 * 64 + ch] = __floats2bfloat162_rn(v0, v1);
      *(__nv_bfloat162*)&g_h1[rowbase + (size_t)(p0 + 8) * 64 + ch] = __floats2bfloat162_rn(v2, v3);
    }
  }
}

// ===== conv2 (64->32 3x3 SAME + ReLU) fused with conv3 (1x1) -> fp32 logits =====
// unchanged orientation: warp = 32 ch (M) x 32 px (N); staging vectorized from NHWC h1.
__global__ __launch_bounds__(512) void conv2_kernel(
    const float* __restrict__ b2,
    const float* __restrict__ w3, const float* __restrict__ b3) {
  extern __shared__ char smem[];
  __nv_bfloat16* xs = (__nv_bfloat16*)smem;
  __nv_bfloat16* ws = (__nv_bfloat16*)(smem + XS_BYTES);
  const int tid = threadIdx.x;
  const int n  = blockIdx.z;
  const int h0 = blockIdx.y * 8;
  const int w0 = blockIdx.x * 64;

  {
    const uint4* src = (const uint4*)g_w2b;
    uint4* dst = (uint4*)ws;
    for (int i = tid; i < WS2_BYTES / 16; i += 512) dst[i] = src[i];
  }
  for (int i = tid; i < 5280; i += 512) {
    int pix = i >> 3, seg = i & 7;
    int r = pix / 66, col = pix - r * 66;
    int h = h0 - 1 + r, w = w0 - 1 + col;
    uint4 v = make_uint4(0u, 0u, 0u, 0u);
    if ((unsigned)h < (unsigned)H_IMG && (unsigned)w < (unsigned)W_IMG)
      v = *(const uint4*)&g_h1[((size_t)(n * H_IMG + h) * W_IMG + w) * 64 + seg * 8];
    *(uint4*)((char*)xs + pix * 144 + seg * 16) = v;
  }
  __syncthreads();

  const int lane = tid & 31, wid = tid >> 5;
  const int g = lane >> 2, tg = lane & 3;
  const int wn = wid & 7;
  const int wh = wid >> 3;   // pixel half

  const unsigned ws_sh = (unsigned)__cvta_generic_to_shared(ws);
  const unsigned xs_sh = (unsigned)__cvta_generic_to_shared(xs);
  const unsigned aLane = (unsigned)(((lane >> 3) & 1) * 8 + (lane & 7)) * 1168
                       + (unsigned)(lane >> 4) * 16;
  const unsigned pixLane = (unsigned)((lane >> 4) * 8 + (lane & 7)) * 144
                         + (unsigned)((lane >> 3) & 1) * 16;

  float acc[2][4][4];
#pragma unroll
  for (int a = 0; a < 2; a++)
#pragma unroll
    for (int q = 0; q < 4; q++)
#pragma unroll
      for (int r = 0; r < 4; r++) acc[a][q][r] = 0.f;

#pragma unroll 1
  for (int tap = 0; tap < 9; ++tap) {
    const int dy = tap / 3, dx = tap - dy * 3;
    const unsigned bTap = xs_sh + (unsigned)(((wn + dy) * 66) + wh * 32 + dx) * 144 + pixLane;
    const unsigned aTap = ws_sh + aLane + (unsigned)tap * 128;
#pragma unroll
    for (int cs = 0; cs < 4; ++cs) {
      unsigned a0, a1, a2, a3, a4, a5, a6, a7;
      ldsm_x4(a0, a1, a2, a3, aTap + cs * 32);            // ch 0..15
      ldsm_x4(a4, a5, a6, a7, aTap + cs * 32 + 18688);    // ch 16..31
#pragma unroll
      for (int np = 0; np < 2; ++np) {
        unsigned b0, b1r, b2, b3;
        ldsm_x4(b0, b1r, b2, b3, bTap + np * 2304 + cs * 32);
        mma16816(acc[0][2 * np],     a0, a1, a2, a3, b0, b1r);
        mma16816(acc[1][2 * np],     a4, a5, a6, a7, b0, b1r);
        mma16816(acc[0][2 * np + 1], a0, a1, a2, a3, b2, b3);
        mma16816(acc[1][2 * np + 1], a4, a5, a6, a7, b2, b3);
      }
    }
  }

  const float w3v0 = w3[g],      w3v1 = w3[g + 8];
  const float w3v2 = w3[g + 16], w3v3 = w3[g + 24];
  const float b2v0 = b2[g],      b2v1 = b2[g + 8];
  const float b2v2 = b2[g + 16], b2v3 = b2[g + 24];
  const float b3v = b3[0];
  const int h = h0 + wn;
  float* heat = g_heat + (size_t)n * NPIX + (size_t)h * W_IMG + w0 + wh * 32;
#pragma unroll
  for (int nt = 0; nt < 4; ++nt) {
    float s0 = fmaxf(acc[0][nt][0] + b2v0, 0.f) * w3v0
             + fmaxf(acc[0][nt][2] + b2v1, 0.f) * w3v1
             + fmaxf(acc[1][nt][0] + b2v2, 0.f) * w3v2
             + fmaxf(acc[1][nt][2] + b2v3, 0.f) * w3v3;
    float s1 = fmaxf(acc[0][nt][1] + b2v0, 0.f) * w3v0
             + fmaxf(acc[0][nt][3] + b2v1, 0.f) * w3v1
             + fmaxf(acc[1][nt][1] + b2v2, 0.f) * w3v2
             + fmaxf(acc[1][nt][3] + b2v3, 0.f) * w3v3;
#pragma unroll
    for (int off = 4; off < 32; off <<= 1) {
      s0 += __shfl_xor_sync(0xffffffffu, s0, off);
      s1 += __shfl_xor_sync(0xffffffffu, s1, off);
    }
    if (g == 0) {
      heat[nt * 8 + 2 * tg]     = s0 + b3v;
      heat[nt * 8 + 2 * tg + 1] = s1 + b3v;
    }
  }
}

// ============== candidate top-16 per image (approx logits) ==============
__global__ __launch_bounds__(1024) void cand_kernel() {
  __shared__ float sv[2048];
  __shared__ int   si[2048];
  const int n = blockIdx.x;
  const int tid = threadIdx.x;
  const float* heat = g_heat + (size_t)n * NPIX;
  float v0 = -FLT_MAX, v1 = -FLT_MAX;
  int i0 = 0x7fffffff, i1 = 0x7fffffff;
  for (int i = tid; i < NPIX; i += 1024) {
    float v = heat[i];
    if (v > v0) { v1 = v0; i1 = i0; v0 = v; i0 = i; }
    else if (v > v1) { v1 = v; i1 = i; }
  }
  sv[tid * 2] = v0; si[tid * 2] = i0;
  sv[tid * 2 + 1] = v1; si[tid * 2 + 1] = i1;
  __syncthreads();
  if (tid == 0) {
    float bv[NCAND]; int bi[NCAND];
#pragma unroll
    for (int j = 0; j < NCAND; j++) { bv[j] = -FLT_MAX; bi[j] = 0x7fffffff; }
    for (int e = 0; e < 2048; e++) {
      float v = sv[e]; int id = si[e];
      if (v > bv[NCAND - 1] || (v == bv[NCAND - 1] && id < bi[NCAND - 1])) {
        int j = NCAND - 1;
        while (j > 0 && (v > bv[j - 1] || (v == bv[j - 1] && id < bi[j - 1]))) {
          bv[j] = bv[j - 1]; bi[j] = bi[j - 1]; j--;
        }
        bv[j] = v; bi[j] = id;
      }
    }
    for (int j = 0; j < NCAND; j++) g_cand[n * NCAND + j] = bi[j];
  }
}

// ============== exact fp32 refinement of candidate logits ==============
__global__ __launch_bounds__(288) void refine_kernel(
    const float* __restrict__ x,
    const float* __restrict__ w1, const float* __restrict__ b1,
    const float* __restrict__ w2, const float* __restrict__ b2,
    const float* __restrict__ w3, const float* __restrict__ b3) {
  extern __shared__ float rs[];
  float* ws1  = rs + ROFF_WS1;
  float* xp   = rs + ROFF_XP;
  float* h1p  = rs + ROFF_H1;
  float* part = rs + ROFF_PART;
  float* s2   = rs + ROFF_S2;
  const int cand = blockIdx.x;
  const int n = cand / NCAND;
  const int tid = threadIdx.x;
  const int pix = g_cand[cand];
  const int hc = pix / W_IMG, wc = pix % W_IMG;

  for (int i = tid; i < 64 * 576; i += 288) {
    int c = i / 576, j = i - c * 576;
    ws1[c * 577 + j] = w1[i];
  }
  for (int i = tid; i < 64 * 25; i += 288) {
    int c = i / 25, p = i - c * 25;
    int y = hc - 2 + p / 5, w = wc - 2 + p % 5;
    float v = 0.f;
    if ((unsigned)y < (unsigned)H_IMG && (unsigned)w < (unsigned)W_IMG)
      v = x[((size_t)(n * C_IN + c) * H_IMG + y) * W_IMG + w];
    xp[c * 28 + p] = v;
  }
  __syncthreads();

  for (int i = tid; i < 576; i += 288) {
    int pos = i >> 6, c = i & 63;
    int py = pos / 3, px = pos - py * 3;
    int yy = hc - 1 + py, xx = wc - 1 + px;
    float s = 0.f;
    if ((unsigned)yy < (unsigned)H_IMG && (unsigned)xx < (unsigned)W_IMG) {
      const float* wrow = ws1 + c * 577;
      for (int ic = 0; ic < 64; ic++) {
#pragma unroll
        for (int ty = 0; ty < 3; ty++)
#pragma unroll
          for (int tx = 0; tx < 3; tx++)
            s += xp[ic * 28 + (py + ty) * 5 + (px + tx)] * wrow[ic * 9 + ty * 3 + tx];
      }
      s = fmaxf(s + b1[c], 0.f);
    }
    h1p[pos * 65 + c] = s;
  }
  __syncthreads();

  {
    int ch = tid / 9, pos = tid - ch * 9;
    float s = 0.f;
    const float* wrow = w2 + (size_t)ch * 576;
    for (int ic = 0; ic < 64; ic++)
      s += h1p[pos * 65 + ic] * wrow[ic * 9 + pos];
    part[ch * 9 + pos] = s;
  }
  __syncthreads();
  if (tid < 32) {
    float s = 0.f;
#pragma unroll
    for (int p = 0; p < 9; p++) s += part[tid * 9 + p];
    s2[tid] = fmaxf(s + b2[tid], 0.f) * w3[tid];
  }
  __syncthreads();
  if (tid == 0) {
    float t = b3[0];
    for (int j = 0; j < 32; j++) t += s2[j];
    g_rlogit[cand] = t;
  }
}

// ============== final: top-2 per image from refined logits -> rois ==============
__global__ __launch_bounds__(96) void final_kernel(float* __restrict__ out) {
  __shared__ float hc_s[B_IMG * K_ROIS], wc_s[B_IMG * K_ROIS];
  const int tid = threadIdx.x;
  if (tid < B_IMG) {
    float v1 = -FLT_MAX, v2 = -FLT_MAX;
    int p1 = 0x7fffffff, p2 = 0x7fffffff;
    for (int j = 0; j < NCAND; j++) {
      float v = g_rlogit[tid * NCAND + j];
      int p = g_cand[tid * NCAND + j];
      if (v > v1 || (v == v1 && p < p1)) { v2 = v1; p2 = p1; v1 = v; p1 = p; }
      else if (v > v2 || (v == v2 && p < p2)) { v2 = v; p2 = p; }
    }
    hc_s[tid * 2]     = (float)(p1 / W_IMG);
    wc_s[tid * 2]     = (float)(p1 % W_IMG);
    hc_s[tid * 2 + 1] = (float)(p2 / W_IMG);
    wc_s[tid * 2 + 1] = (float)(p2 % W_IMG);
  }
  __syncthreads();
  for (int i = tid; i < NUM_FRAMES * B_IMG * K_ROIS * 4; i += 96) {
    int f = i / (B_IMG * K_ROIS * 4);
    int rem = i - f * (B_IMG * K_ROIS * 4);
    int j = rem >> 2, comp = rem & 3;
    float val;
    if (comp == 0)      val = (float)(j >> 1);
    else if (comp == 1) val = (float)f;
    else if (comp == 2) val = hc_s[j];
    else                val = wc_s[j];
    out[i] = val;
  }
}

// ---------------- launch ----------------
extern "C" void kernel_launch(void* const* d_in, const int* in_sizes, int n_in,
                              void* d_out, int out_size) {
  const float* x  = (const float*)d_in[0];
  const float* w1 = (const float*)d_in[1];
  const float* b1 = (const float*)d_in[2];
  const float* w2 = (const float*)d_in[3];
  const float* b2 = (const float*)d_in[4];
  const float* w3 = (const float*)d_in[5];
  const float* b3 = (const float*)d_in[6];
  float* out = (float*)d_out;

  cudaFuncSetAttribute(conv1_kernel, cudaFuncAttributeMaxDynamicSharedMemorySize, SMEM1);
  cudaFuncSetAttribute(conv2_kernel, cudaFuncAttributeMaxDynamicSharedMemorySize, SMEM2);
  cudaFuncSetAttribute(refine_kernel, cudaFuncAttributeMaxDynamicSharedMemorySize, RSMEM_BYTES);

  prep_x_kernel<<<dim3(8, 288, 8), 256>>>(x);
  prep_w_kernel<<<64, 512>>>(w1, w2);
  conv1_kernel<<<dim3(8, 36, 8), 512, SMEM1>>>(b1);
  conv2_kernel<<<dim3(8, 36, 8), 512, SMEM2>>>(b2, w3, b3);
  cand_kernel<<<8, 1024>>>();
  refine_kernel<<<B_IMG * NCAND, 288, RSMEM_BYTES>>>(x, w1, b1, w2, b2, w3, b3);
  final_kernel<<<1, 96>>>(out);
}